// round 12
// baseline (speedup 1.0000x reference)
#include <cuda_runtime.h>
#include <cuda_fp16.h>
#include <math.h>

// Problem sizes
#define NB    64
#define NS    256
#define NC    16
#define ND    512
#define N4D   2048
#define NVIS  16384            // NB*NS
#define VOCABI 20000

// Recurrence config: 4 batch-groups x 32 unit-groups = 128 CTAs (1/SM)
#define NCTA_REC 128
#define BGRPS    4
#define BPC      16            // batches per CTA
#define UNITS    16            // hidden units per CTA
#define GROWS    64            // gate rows per CTA (UNITS*4)
#define NGRP     32            // CTAs per batch group
#define NARRV    256           // arrivals per step per group (32 CTAs x 8 warps)
#define WSTRIDE  260           // u32 stride for a 512-half row (+16B pad) = 1040 B
#define ROWB     1040          // bytes per padded smem row

// lstm_rec smem byte offsets
#define SM_WHH  0
#define SM_WSZ  (GROWS * WSTRIDE * 4)               // 66560
#define SM_WIH  SM_WSZ                              // 66560
#define SM_H    (2 * SM_WSZ)                        // 133120
#define SM_HSZ  (BPC * WSTRIDE * 4)                 // 16640
#define SM_X    (SM_H + SM_HSZ)                     // 149760 (2 buffers)
#define SM_TOT  (SM_X + 2 * SM_HSZ)                 // 183040

// ---------------- device scratch (static globals: no allocation) ----------------
__device__ __half        g_Wih16[N4D * ND];
__device__ __half        g_Wh16[N4D * ND];
__device__ __half        g_X16[NVIS * ND];          // [s][b][d] fp16
__device__ __align__(128) __half g_h16[2 * NB * ND]; // double buffered h (fp16)
__device__ float         g_final[NB * ND];
__device__ unsigned      g_arr[BGRPS * 32];          // 4 counters, 128B apart

// ---------------- helpers ----------------
__device__ __forceinline__ void mma_f16(float* c, const unsigned* a, const unsigned* b) {
    asm volatile(
        "mma.sync.aligned.m16n8k16.row.col.f32.f16.f16.f32 "
        "{%0,%1,%2,%3}, {%4,%5,%6,%7}, {%8,%9}, {%0,%1,%2,%3};\n"
        : "+f"(c[0]), "+f"(c[1]), "+f"(c[2]), "+f"(c[3])
        : "r"(a[0]), "r"(a[1]), "r"(a[2]), "r"(a[3]), "r"(b[0]), "r"(b[1]));
}

__device__ __forceinline__ void ldsm4(unsigned* r, unsigned saddr) {
    asm volatile("ldmatrix.sync.aligned.m8n8.x4.shared.b16 {%0,%1,%2,%3}, [%4];"
                 : "=r"(r[0]), "=r"(r[1]), "=r"(r[2]), "=r"(r[3]) : "r"(saddr));
}
__device__ __forceinline__ void ldsm2(unsigned* r, unsigned saddr) {
    asm volatile("ldmatrix.sync.aligned.m8n8.x2.shared.b16 {%0,%1}, [%2];"
                 : "=r"(r[0]), "=r"(r[1]) : "r"(saddr));
}
__device__ __forceinline__ void cp16(unsigned s, const void* g) {
    asm volatile("cp.async.cg.shared.global [%0], [%1], 16;\n" :: "r"(s), "l"(g));
}
__device__ __forceinline__ void cp_commit() {
    asm volatile("cp.async.commit_group;\n" ::: "memory");
}
template<int N> __device__ __forceinline__ void cp_wait() {
    asm volatile("cp.async.wait_group %0;\n" :: "n"(N) : "memory");
}

__device__ __forceinline__ void arrive_release(unsigned* p) {
    asm volatile("red.release.gpu.global.add.u32 [%0], 1;" :: "l"(p) : "memory");
}
__device__ __forceinline__ unsigned ld_acquire(const unsigned* p) {
    unsigned v;
    asm volatile("ld.acquire.gpu.global.u32 %0, [%1];" : "=r"(v) : "l"(p) : "memory");
    return v;
}

__device__ __forceinline__ float sigf(float x) {
    float e = __expf(-x);
    return __fdividef(1.f, 1.f + e);
}
__device__ __forceinline__ float tanhfast(float x) {
    float e = __expf(-2.f * fabsf(x));
    float r = __fdividef(1.f - e, 1.f + e);
    return copysignf(r, x);
}

// ---------------- kernel 1: weight prep (fp32 -> fp16) ----------------
__global__ void prep_weights(const float* __restrict__ wih, const float* __restrict__ whh) {
    int i = blockIdx.x * 256 + threadIdx.x;
    if (i < N4D * ND) {
        g_Wih16[i] = __float2half_rn(wih[i]);
        g_Wh16[i]  = __float2half_rn(whh[i]);
    }
}

// ---------------- kernel 2: embedding-bag sum -> X fp16 [s][b][d] ----------------
__global__ void embed_kernel(const int* __restrict__ seqs, const float* __restrict__ emb) {
    int vis = blockIdx.x;          // vis = b*256 + s
    int t   = threadIdx.x;         // 0..127
    int b = vis >> 8, s = vis & 255;
    const int* sq = seqs + vis * NC;
    float a0 = 0.f, a1 = 0.f, a2 = 0.f, a3 = 0.f;
#pragma unroll
    for (int c = 0; c < NC; c++) {
        int idx = sq[c];
        if (idx >= VOCABI) continue;          // padding row -> zero
        const float* row = emb + (size_t)idx * ND;
        a0 += row[t];
        a1 += row[t + 128];
        a2 += row[t + 256];
        a3 += row[t + 384];
    }
    __half* dst = g_X16 + ((size_t)s * NB + b) * ND;
    dst[t]       = __float2half_rn(a0);
    dst[t + 128] = __float2half_rn(a1);
    dst[t + 256] = __float2half_rn(a2);
    dst[t + 384] = __float2half_rn(a3);
}

// ---------------- kernel 3: reset state + barriers ----------------
__global__ void reset_kernel() {
    int i = blockIdx.x * 256 + threadIdx.x;
    if (i < 2 * NB * ND / 2) {
        ((unsigned*)g_h16)[i] = 0u;
    }
    if (i < BGRPS * 32) g_arr[i] = 0u;
}

// ---------------- kernel 4: persistent fused LSTM ----------------
// 128 CTAs (1/SM) = 4 batch-groups x 32 unit-groups, 256 threads each.
// gates = x[s]@Wih^T + h[s-1]@Whh^T. Software pipeline:
//  - barrier window: first half of x[s+1]-mma + x[s+2] prefetch
//  - post-staging: second half of x[s]-mma covers h-chunk0 cp.async latency
//  - HMMA accumulation split over 4 chains (xacc,h0,h1,h2)
//  - per-warp arrive/poll barrier (no post-epilogue __syncthreads)
__global__ void __launch_bounds__(256, 1) lstm_rec(const int* __restrict__ lengths) {
    extern __shared__ unsigned smem[];
    char* smc = (char*)smem;

    unsigned sb = (unsigned)__cvta_generic_to_shared(smc);
    unsigned sH_b = sb + SM_H;
    unsigned sX_b = sb + SM_X;

    int t = threadIdx.x, cta = blockIdx.x;
    int wn = t >> 5, lane = t & 31;           // 8 warps, all on N
    int row = lane >> 2, q = lane & 3;

    int bgrp = cta >> 5;            // 0..3
    int ugrp = cta & 31;            // 0..31
    int jbase = ugrp * UNITS;

    // load W slices (fp16) to smem. slot s (0..63): u=s>>2, gate=s&3.
    {
        unsigned* sWhh = (unsigned*)(smc + SM_WHH);
        unsigned* sWih = (unsigned*)(smc + SM_WIH);
        const unsigned* Hsrc = (const unsigned*)g_Wh16;
        const unsigned* Isrc = (const unsigned*)g_Wih16;
        for (int i = t; i < GROWS * 256; i += 256) {
            int s = i >> 8, kw = i & 255;
            int u = s >> 2, gate = s & 3;
            int grow = gate * ND + jbase + u;
            sWhh[s * WSTRIDE + kw] = Hsrc[grow * 256 + kw];
            sWih[s * WSTRIDE + kw] = Isrc[grow * 256 + kw];
        }
    }
    __syncthreads();

    // preload B fragments for both weight sets (loop-invariant)
    unsigned bwh[64], bwi[64];
    {
        unsigned bl = (unsigned)(wn * 8 + (lane & 7)) * ROWB + ((lane >> 3) & 1) * 16;
        unsigned bh_ = sb + SM_WHH + bl;
        unsigned bi_ = sb + SM_WIH + bl;
#pragma unroll
        for (int kc = 0; kc < 32; kc++) {
            ldsm2(&bwh[2 * kc], bh_ + kc * 32);
            ldsm2(&bwi[2 * kc], bi_ + kc * 32);
        }
    }

    // epilogue ownership (warp-local): even-q lanes batch `row`, odd-q `row+8`;
    // unit = 2*wn + (q>>1).
    int parity = q & 1;
    int b_own = bgrp * BPC + row + (parity ? 8 : 0);
    int jglob = jbase + 2 * wn + (q >> 1);
    int len0 = lengths[b_own] - 1;
    float cst = 0.f;

    // ldmatrix A lane addresses (same pattern for h and x tiles)
    unsigned alane = (unsigned)(lane & 15) * ROWB + (lane >> 4) * 16;
    unsigned ahoff = sH_b + alane;

    // h staging: 16 rows x 1024B, 4 chunks of 256B/row; 1 cp16/thread/chunk
    int sr = t >> 4, ssg = t & 15;
    unsigned sdst0 = sH_b + (unsigned)sr * ROWB + ssg * 16;
    size_t ssrc0 = (size_t)sr * 1024 + ssg * 16;

    // x staging addressing: 4 cp16 per thread
    int xr = t >> 6, xc = t & 63;
    unsigned* arrp = &g_arr[bgrp * 32];

    // x tile gmem base for this batch group
    const char* xg_base = (const char*)g_X16 + (size_t)bgrp * (BPC * 1024);

    float xacc[4], h0[4], h1[4], h2[4];

    // ---- prologue: stage x[0]; first-half x-mma; prefetch x[1] ----
    {
#pragma unroll
        for (int k = 0; k < 4; k++) {
            int rw = xr + k * 4;
            cp16(sX_b + (unsigned)rw * ROWB + xc * 16,
                 xg_base + (size_t)rw * 1024 + xc * 16);
        }
        cp_commit();
        cp_wait<0>();
        __syncthreads();
#pragma unroll
        for (int i = 0; i < 4; i++) { xacc[i] = 0.f; h0[i] = 0.f; h1[i] = 0.f; h2[i] = 0.f; }
        unsigned axoff = sX_b + alane;
#pragma unroll
        for (int kc = 0; kc < 16; kc++) {
            unsigned ax[4];
            ldsm4(ax, axoff + kc * 32);
            mma_f16((kc & 1) ? h0 : xacc, ax, &bwi[2 * kc]);
        }
        // prefetch x[1] into buffer 1
        const char* xsrc = xg_base + (size_t)1 * (NB * 1024);
#pragma unroll
        for (int k = 0; k < 4; k++) {
            int rw = xr + k * 4;
            cp16(sX_b + (unsigned)SM_HSZ + (unsigned)rw * ROWB + xc * 16,
                 xsrc + (size_t)rw * 1024 + xc * 16);
        }
        cp_commit();
    }

    for (int step = 0; step < NS; step++) {
        int rd = step & 1;
        int wr = rd ^ 1;

        // ---- issue h staging: 4 K-chunks, one commit group each ----
        // pending per thread entering: [xpf(step+1)] then c0..c3
        {
            const char* hsrc = (const char*)g_h16 + (size_t)rd * (NB * ND * 2)
                             + (size_t)bgrp * (BPC * 1024);
#pragma unroll
            for (int c = 0; c < 4; c++) {
                cp16(sdst0 + c * 256, hsrc + ssrc0 + c * 256);
                cp_commit();
            }
        }

        // ---- second-half x-mma for CURRENT step (covers h-chunk0 latency) ----
        {
            unsigned axoff = sX_b + (unsigned)(step & 1) * (unsigned)SM_HSZ + alane;
#pragma unroll
            for (int kc = 16; kc < 32; kc++) {
                unsigned ax[4];
                ldsm4(ax, axoff + kc * 32);
                mma_f16((kc & 1) ? h2 : h1, ax, &bwi[2 * kc]);
            }
        }

        // ---- h-mma over 4 chunks, 4-way split accumulation ----
#pragma unroll
        for (int c = 0; c < 4; c++) {
            if (c == 0) cp_wait<3>();
            else if (c == 1) cp_wait<2>();
            else if (c == 2) cp_wait<1>();
            else cp_wait<0>();       // also drains x-prefetch(step+1)
            __syncthreads();
#pragma unroll
            for (int j = 0; j < 8; j++) {
                int kc = c * 8 + j;
                unsigned ah[4];
                ldsm4(ah, ahoff + kc * 32);
                float* dst = (j & 2) ? ((j & 1) ? h2 : h1) : ((j & 1) ? h0 : xacc);
                mma_f16(dst, ah, &bwh[2 * kc]);
            }
        }

        // ---- warp-local epilogue via shuffles ----
        {
            float g0 = (xacc[0] + h0[0]) + (h1[0] + h2[0]);
            float g1 = (xacc[1] + h0[1]) + (h1[1] + h2[1]);
            float g2 = (xacc[2] + h0[2]) + (h1[2] + h2[2]);
            float g3 = (xacc[3] + h0[3]) + (h1[3] + h2[3]);
            float s0 = __shfl_xor_sync(0xffffffffu, g0, 1);
            float s1 = __shfl_xor_sync(0xffffffffu, g1, 1);
            float s2 = __shfl_xor_sync(0xffffffffu, g2, 1);
            float s3 = __shfl_xor_sync(0xffffffffu, g3, 1);
            float gi, gf, gg_, go;
            if (!parity) { gi = g0; gf = g1; gg_ = s0; go = s1; }
            else         { gi = s2; gf = s3; gg_ = g2; go = g3; }
            float iv = sigf(gi);
            float fv = sigf(gf);
            float gv = tanhfast(gg_);
            float ov = sigf(go);
            float c = fv * cst + iv * gv;
            cst = c;
            float hv = ov * tanhfast(c);
            g_h16[wr * (NB * ND) + b_own * ND + jglob] = __float2half_rn(hv);
            if (step == len0) g_final[b_own * ND + jglob] = hv;
        }

        if (step == NS - 1) break;  // nothing consumes h after the last step

        // ---- per-warp arrive (release after warp's h writes) ----
        __syncwarp();
        if (lane == 0) arrive_release(arrp);

        // ---- barrier window: zero chains, prefetch x[step+2], first-half
        //      x-mma for step+1 ----
        {
#pragma unroll
            for (int i = 0; i < 4; i++) { xacc[i] = 0.f; h0[i] = 0.f; h1[i] = 0.f; h2[i] = 0.f; }
            int ns2 = (step + 2 < NS) ? step + 2 : 0;
            const char* xsrc = xg_base + (size_t)ns2 * (NB * 1024);
            unsigned xpb = (unsigned)(step & 1) * (unsigned)SM_HSZ;   // buf for s+2
#pragma unroll
            for (int k = 0; k < 4; k++) {
                int rw = xr + k * 4;
                cp16(sX_b + xpb + (unsigned)rw * ROWB + xc * 16,
                     xsrc + (size_t)rw * 1024 + xc * 16);
            }
            cp_commit();

            // first-half x-mma for step+1 (tile visible since chunk3 sync)
            unsigned axoff = sX_b + (unsigned)((step + 1) & 1) * (unsigned)SM_HSZ + alane;
#pragma unroll
            for (int kc = 0; kc < 16; kc++) {
                unsigned ax[4];
                ldsm4(ax, axoff + kc * 32);
                mma_f16((kc & 1) ? h0 : xacc, ax, &bwi[2 * kc]);
            }
        }

        // ---- per-warp wait ----
        if (lane == 0) {
            unsigned target = (unsigned)NARRV * (unsigned)(step + 1);
            while (ld_acquire(arrp) < target) { }
        }
        __syncwarp();
    }
}

// ---------------- kernel 5: output projection ----------------
__global__ void final_out(const float* __restrict__ w_out, const float* __restrict__ b_out,
                          float* __restrict__ out) {
    int b = blockIdx.x;
    int t = threadIdx.x;
    int r = t >> 5, lane = t & 31;
    float s = 0.f;
    for (int k = lane; k < ND; k += 32)
        s += g_final[b * ND + k] * w_out[r * ND + k];
#pragma unroll
    for (int off = 16; off; off >>= 1) s += __shfl_down_sync(0xffffffffu, s, off);
    if (lane == 0) out[b * 2 + r] = s + b_out[r];
}

// ---------------- launch ----------------
extern "C" void kernel_launch(void* const* d_in, const int* in_sizes, int n_in,
                              void* d_out, int out_size) {
    const int*   seqs    = (const int*)d_in[0];
    const int*   lengths = (const int*)d_in[1];
    const float* emb     = (const float*)d_in[2];
    const float* wih     = (const float*)d_in[3];
    const float* whh     = (const float*)d_in[4];
    const float* wout    = (const float*)d_in[5];
    const float* bout    = (const float*)d_in[6];
    float* out = (float*)d_out;

    cudaFuncSetAttribute(lstm_rec, cudaFuncAttributeMaxDynamicSharedMemorySize, SM_TOT);

    prep_weights<<<4096, 256>>>(wih, whh);
    embed_kernel<<<NVIS, 128>>>(seqs, emb);
    reset_kernel<<<128, 256>>>();
    lstm_rec<<<NCTA_REC, 256, SM_TOT>>>(lengths);
    final_out<<<NB, 64>>>(wout, bout, out);
}

// round 13
// speedup vs baseline: 1.0556x; 1.0556x over previous
#include <cuda_runtime.h>
#include <cuda_fp16.h>
#include <math.h>

// Problem sizes
#define NB    64
#define NS    256
#define NC    16
#define ND    512
#define N4D   2048
#define NVIS  16384            // NB*NS
#define VOCABI 20000

// Recurrence config: 4 batch-groups x 32 unit-groups = 128 CTAs (1/SM)
#define NCTA_REC 128
#define BGRPS    4
#define BPC      16            // batches per CTA
#define UNITS    16            // hidden units per CTA
#define GROWS    64            // gate rows per CTA (UNITS*4)
#define NGRP     32            // CTAs per batch group
#define WSTRIDE  260           // u32 stride for a 512-half row (+16B pad) = 1040 B
#define ROWB     1040          // bytes per padded smem row

// lstm_rec smem byte offsets
#define SM_WHH  0
#define SM_WSZ  (GROWS * WSTRIDE * 4)               // 66560
#define SM_WIH  SM_WSZ                              // 66560
#define SM_H    (2 * SM_WSZ)                        // 133120
#define SM_HSZ  (BPC * WSTRIDE * 4)                 // 16640
#define SM_X    (SM_H + SM_HSZ)                     // 149760 (2 buffers)
#define SM_TOT  (SM_X + 2 * SM_HSZ)                 // 183040

// ---------------- device scratch (static globals: no allocation) ----------------
__device__ __half        g_Wih16[N4D * ND];
__device__ __half        g_Wh16[N4D * ND];
__device__ __half        g_X16[NVIS * ND];          // [s][b][d] fp16
__device__ __align__(128) __half g_h16[2 * NB * ND]; // double buffered h (fp16)
__device__ float         g_final[NB * ND];
__device__ unsigned      g_arr[BGRPS * 32];          // 4 counters, 128B apart

// ---------------- helpers ----------------
__device__ __forceinline__ void mma_f16(float* c, const unsigned* a, const unsigned* b) {
    asm volatile(
        "mma.sync.aligned.m16n8k16.row.col.f32.f16.f16.f32 "
        "{%0,%1,%2,%3}, {%4,%5,%6,%7}, {%8,%9}, {%0,%1,%2,%3};\n"
        : "+f"(c[0]), "+f"(c[1]), "+f"(c[2]), "+f"(c[3])
        : "r"(a[0]), "r"(a[1]), "r"(a[2]), "r"(a[3]), "r"(b[0]), "r"(b[1]));
}

__device__ __forceinline__ void ldsm4(unsigned* r, unsigned saddr) {
    asm volatile("ldmatrix.sync.aligned.m8n8.x4.shared.b16 {%0,%1,%2,%3}, [%4];"
                 : "=r"(r[0]), "=r"(r[1]), "=r"(r[2]), "=r"(r[3]) : "r"(saddr));
}
__device__ __forceinline__ void ldsm2(unsigned* r, unsigned saddr) {
    asm volatile("ldmatrix.sync.aligned.m8n8.x2.shared.b16 {%0,%1}, [%2];"
                 : "=r"(r[0]), "=r"(r[1]) : "r"(saddr));
}
__device__ __forceinline__ void cp16(unsigned s, const void* g) {
    asm volatile("cp.async.cg.shared.global [%0], [%1], 16;\n" :: "r"(s), "l"(g));
}
__device__ __forceinline__ void cp_commit() {
    asm volatile("cp.async.commit_group;\n" ::: "memory");
}
template<int N> __device__ __forceinline__ void cp_wait() {
    asm volatile("cp.async.wait_group %0;\n" :: "n"(N) : "memory");
}

__device__ __forceinline__ void arrive_release(unsigned* p) {
    asm volatile("red.release.gpu.global.add.u32 [%0], 1;" :: "l"(p) : "memory");
}
__device__ __forceinline__ unsigned ld_acquire(const unsigned* p) {
    unsigned v;
    asm volatile("ld.acquire.gpu.global.u32 %0, [%1];" : "=r"(v) : "l"(p) : "memory");
    return v;
}

__device__ __forceinline__ float sigf(float x) {
    float e = __expf(-x);
    return __fdividef(1.f, 1.f + e);
}
__device__ __forceinline__ float tanhfast(float x) {
    float e = __expf(-2.f * fabsf(x));
    float r = __fdividef(1.f - e, 1.f + e);
    return copysignf(r, x);
}

// ---------------- kernel 1: weight prep (fp32 -> fp16) ----------------
__global__ void prep_weights(const float* __restrict__ wih, const float* __restrict__ whh) {
    int i = blockIdx.x * 256 + threadIdx.x;
    if (i < N4D * ND) {
        g_Wih16[i] = __float2half_rn(wih[i]);
        g_Wh16[i]  = __float2half_rn(whh[i]);
    }
}

// ---------------- kernel 2: embedding-bag sum -> X fp16 [s][b][d] ----------------
__global__ void embed_kernel(const int* __restrict__ seqs, const float* __restrict__ emb) {
    int vis = blockIdx.x;          // vis = b*256 + s
    int t   = threadIdx.x;         // 0..127
    int b = vis >> 8, s = vis & 255;
    const int* sq = seqs + vis * NC;
    float a0 = 0.f, a1 = 0.f, a2 = 0.f, a3 = 0.f;
#pragma unroll
    for (int c = 0; c < NC; c++) {
        int idx = sq[c];
        if (idx >= VOCABI) continue;          // padding row -> zero
        const float* row = emb + (size_t)idx * ND;
        a0 += row[t];
        a1 += row[t + 128];
        a2 += row[t + 256];
        a3 += row[t + 384];
    }
    __half* dst = g_X16 + ((size_t)s * NB + b) * ND;
    dst[t]       = __float2half_rn(a0);
    dst[t + 128] = __float2half_rn(a1);
    dst[t + 256] = __float2half_rn(a2);
    dst[t + 384] = __float2half_rn(a3);
}

// ---------------- kernel 3: reset state + barriers ----------------
__global__ void reset_kernel() {
    int i = blockIdx.x * 256 + threadIdx.x;
    if (i < 2 * NB * ND / 2) {
        ((unsigned*)g_h16)[i] = 0u;
    }
    if (i < BGRPS * 32) g_arr[i] = 0u;
}

// ---------------- kernel 4: persistent fused LSTM ----------------
// 128 CTAs (1/SM) = 4 batch-groups x 32 unit-groups, 256 threads each.
// gates = x[s]@Wih^T + h[s-1]@Whh^T. Software pipeline:
//  - barrier window (between per-CTA arrive and poll): first half of
//    x[s+1]-mma + x[s+2] prefetch
//  - post-staging: second half of x[s]-mma covers h-chunk0 cp.async latency
//  - HMMA accumulation split over 4 chains (xacc,h0,h1,h2)
//  - per-CTA arrive/poll barrier (32 arrivals, 32 pollers)
__global__ void __launch_bounds__(256, 1) lstm_rec(const int* __restrict__ lengths) {
    extern __shared__ unsigned smem[];
    char* smc = (char*)smem;

    unsigned sb = (unsigned)__cvta_generic_to_shared(smc);
    unsigned sH_b = sb + SM_H;
    unsigned sX_b = sb + SM_X;

    int t = threadIdx.x, cta = blockIdx.x;
    int wn = t >> 5, lane = t & 31;           // 8 warps, all on N
    int row = lane >> 2, q = lane & 3;

    int bgrp = cta >> 5;            // 0..3
    int ugrp = cta & 31;            // 0..31
    int jbase = ugrp * UNITS;

    // load W slices (fp16) to smem. slot s (0..63): u=s>>2, gate=s&3.
    {
        unsigned* sWhh = (unsigned*)(smc + SM_WHH);
        unsigned* sWih = (unsigned*)(smc + SM_WIH);
        const unsigned* Hsrc = (const unsigned*)g_Wh16;
        const unsigned* Isrc = (const unsigned*)g_Wih16;
        for (int i = t; i < GROWS * 256; i += 256) {
            int s = i >> 8, kw = i & 255;
            int u = s >> 2, gate = s & 3;
            int grow = gate * ND + jbase + u;
            sWhh[s * WSTRIDE + kw] = Hsrc[grow * 256 + kw];
            sWih[s * WSTRIDE + kw] = Isrc[grow * 256 + kw];
        }
    }
    __syncthreads();

    // preload B fragments for both weight sets (loop-invariant)
    unsigned bwh[64], bwi[64];
    {
        unsigned bl = (unsigned)(wn * 8 + (lane & 7)) * ROWB + ((lane >> 3) & 1) * 16;
        unsigned bh_ = sb + SM_WHH + bl;
        unsigned bi_ = sb + SM_WIH + bl;
#pragma unroll
        for (int kc = 0; kc < 32; kc++) {
            ldsm2(&bwh[2 * kc], bh_ + kc * 32);
            ldsm2(&bwi[2 * kc], bi_ + kc * 32);
        }
    }

    // epilogue ownership (warp-local): even-q lanes batch `row`, odd-q `row+8`;
    // unit = 2*wn + (q>>1).
    int parity = q & 1;
    int b_own = bgrp * BPC + row + (parity ? 8 : 0);
    int jglob = jbase + 2 * wn + (q >> 1);
    int len0 = lengths[b_own] - 1;
    float cst = 0.f;

    // ldmatrix A lane addresses (same pattern for h and x tiles)
    unsigned alane = (unsigned)(lane & 15) * ROWB + (lane >> 4) * 16;
    unsigned ahoff = sH_b + alane;

    // h staging: 16 rows x 1024B, 4 chunks of 256B/row; 1 cp16/thread/chunk
    int sr = t >> 4, ssg = t & 15;
    unsigned sdst0 = sH_b + (unsigned)sr * ROWB + ssg * 16;
    size_t ssrc0 = (size_t)sr * 1024 + ssg * 16;

    // x staging addressing: 4 cp16 per thread
    int xr = t >> 6, xc = t & 63;
    unsigned* arrp = &g_arr[bgrp * 32];

    // x tile gmem base for this batch group
    const char* xg_base = (const char*)g_X16 + (size_t)bgrp * (BPC * 1024);

    float xacc[4], h0[4], h1[4], h2[4];

    // ---- prologue: stage x[0]; first-half x-mma; prefetch x[1] ----
    {
#pragma unroll
        for (int k = 0; k < 4; k++) {
            int rw = xr + k * 4;
            cp16(sX_b + (unsigned)rw * ROWB + xc * 16,
                 xg_base + (size_t)rw * 1024 + xc * 16);
        }
        cp_commit();
        cp_wait<0>();
        __syncthreads();
#pragma unroll
        for (int i = 0; i < 4; i++) { xacc[i] = 0.f; h0[i] = 0.f; h1[i] = 0.f; h2[i] = 0.f; }
        unsigned axoff = sX_b + alane;
#pragma unroll
        for (int kc = 0; kc < 16; kc++) {
            unsigned ax[4];
            ldsm4(ax, axoff + kc * 32);
            mma_f16((kc & 1) ? h0 : xacc, ax, &bwi[2 * kc]);
        }
        // prefetch x[1] into buffer 1
        const char* xsrc = xg_base + (size_t)1 * (NB * 1024);
#pragma unroll
        for (int k = 0; k < 4; k++) {
            int rw = xr + k * 4;
            cp16(sX_b + (unsigned)SM_HSZ + (unsigned)rw * ROWB + xc * 16,
                 xsrc + (size_t)rw * 1024 + xc * 16);
        }
        cp_commit();
    }

    for (int step = 0; step < NS; step++) {
        int rd = step & 1;
        int wr = rd ^ 1;

        // ---- issue h staging: 4 K-chunks, one commit group each ----
        // pending per thread entering: [xpf(step+1)] then c0..c3
        {
            const char* hsrc = (const char*)g_h16 + (size_t)rd * (NB * ND * 2)
                             + (size_t)bgrp * (BPC * 1024);
#pragma unroll
            for (int c = 0; c < 4; c++) {
                cp16(sdst0 + c * 256, hsrc + ssrc0 + c * 256);
                cp_commit();
            }
        }

        // ---- second-half x-mma for CURRENT step (covers h-chunk0 latency) ----
        {
            unsigned axoff = sX_b + (unsigned)(step & 1) * (unsigned)SM_HSZ + alane;
#pragma unroll
            for (int kc = 16; kc < 32; kc++) {
                unsigned ax[4];
                ldsm4(ax, axoff + kc * 32);
                mma_f16((kc & 1) ? h2 : h1, ax, &bwi[2 * kc]);
            }
        }

        // ---- h-mma over 4 chunks, 4-way split accumulation ----
#pragma unroll
        for (int c = 0; c < 4; c++) {
            if (c == 0) cp_wait<3>();
            else if (c == 1) cp_wait<2>();
            else if (c == 2) cp_wait<1>();
            else cp_wait<0>();       // also drains x-prefetch(step+1)
            __syncthreads();
#pragma unroll
            for (int j = 0; j < 8; j++) {
                int kc = c * 8 + j;
                unsigned ah[4];
                ldsm4(ah, ahoff + kc * 32);
                float* dst = (j & 2) ? ((j & 1) ? h2 : h1) : ((j & 1) ? h0 : xacc);
                mma_f16(dst, ah, &bwh[2 * kc]);
            }
        }

        // ---- warp-local epilogue via shuffles ----
        {
            float g0 = (xacc[0] + h0[0]) + (h1[0] + h2[0]);
            float g1 = (xacc[1] + h0[1]) + (h1[1] + h2[1]);
            float g2 = (xacc[2] + h0[2]) + (h1[2] + h2[2]);
            float g3 = (xacc[3] + h0[3]) + (h1[3] + h2[3]);
            float s0 = __shfl_xor_sync(0xffffffffu, g0, 1);
            float s1 = __shfl_xor_sync(0xffffffffu, g1, 1);
            float s2 = __shfl_xor_sync(0xffffffffu, g2, 1);
            float s3 = __shfl_xor_sync(0xffffffffu, g3, 1);
            float gi, gf, gg_, go;
            if (!parity) { gi = g0; gf = g1; gg_ = s0; go = s1; }
            else         { gi = s2; gf = s3; gg_ = g2; go = g3; }
            float iv = sigf(gi);
            float fv = sigf(gf);
            float gv = tanhfast(gg_);
            float ov = sigf(go);
            float c = fv * cst + iv * gv;
            cst = c;
            float hv = ov * tanhfast(c);
            g_h16[wr * (NB * ND) + b_own * ND + jglob] = __float2half_rn(hv);
            if (step == len0) g_final[b_own * ND + jglob] = hv;
        }
        __syncthreads();            // all warps' h writes (and x tile reads) done

        if (step == NS - 1) break;  // nothing consumes h after the last step

        // ---- per-CTA arrive (release; bar.sync ordered all CTA writes) ----
        if (t == 0) arrive_release(arrp);

        // ---- barrier window: zero chains, prefetch x[step+2], first-half
        //      x-mma for step+1 ----
        {
#pragma unroll
            for (int i = 0; i < 4; i++) { xacc[i] = 0.f; h0[i] = 0.f; h1[i] = 0.f; h2[i] = 0.f; }
            int ns2 = (step + 2 < NS) ? step + 2 : 0;
            const char* xsrc = xg_base + (size_t)ns2 * (NB * 1024);
            unsigned xpb = (unsigned)(step & 1) * (unsigned)SM_HSZ;   // buf for s+2
#pragma unroll
            for (int k = 0; k < 4; k++) {
                int rw = xr + k * 4;
                cp16(sX_b + xpb + (unsigned)rw * ROWB + xc * 16,
                     xsrc + (size_t)rw * 1024 + xc * 16);
            }
            cp_commit();

            // first-half x-mma for step+1 (tile visible since chunk3 sync)
            unsigned axoff = sX_b + (unsigned)((step + 1) & 1) * (unsigned)SM_HSZ + alane;
#pragma unroll
            for (int kc = 0; kc < 16; kc++) {
                unsigned ax[4];
                ldsm4(ax, axoff + kc * 32);
                mma_f16((kc & 1) ? h0 : xacc, ax, &bwi[2 * kc]);
            }
        }

        // ---- per-CTA wait (32 CTAs of this batch group) ----
        if (t == 0) {
            unsigned target = (unsigned)NGRP * (unsigned)(step + 1);
            while (ld_acquire(arrp) < target) { }
        }
        __syncthreads();
    }
}

// ---------------- kernel 5: output projection ----------------
__global__ void final_out(const float* __restrict__ w_out, const float* __restrict__ b_out,
                          float* __restrict__ out) {
    int b = blockIdx.x;
    int t = threadIdx.x;
    int r = t >> 5, lane = t & 31;
    float s = 0.f;
    for (int k = lane; k < ND; k += 32)
        s += g_final[b * ND + k] * w_out[r * ND + k];
#pragma unroll
    for (int off = 16; off; off >>= 1) s += __shfl_down_sync(0xffffffffu, s, off);
    if (lane == 0) out[b * 2 + r] = s + b_out[r];
}

// ---------------- launch ----------------
extern "C" void kernel_launch(void* const* d_in, const int* in_sizes, int n_in,
                              void* d_out, int out_size) {
    const int*   seqs    = (const int*)d_in[0];
    const int*   lengths = (const int*)d_in[1];
    const float* emb     = (const float*)d_in[2];
    const float* wih     = (const float*)d_in[3];
    const float* whh     = (const float*)d_in[4];
    const float* wout    = (const float*)d_in[5];
    const float* bout    = (const float*)d_in[6];
    float* out = (float*)d_out;

    cudaFuncSetAttribute(lstm_rec, cudaFuncAttributeMaxDynamicSharedMemorySize, SM_TOT);

    prep_weights<<<4096, 256>>>(wih, whh);
    embed_kernel<<<NVIS, 128>>>(seqs, emb);
    reset_kernel<<<128, 256>>>();
    lstm_rec<<<NCTA_REC, 256, SM_TOT>>>(lengths);
    final_out<<<NB, 64>>>(wout, bout, out);
}